// round 8
// baseline (speedup 1.0000x reference)
#include <cuda_runtime.h>
#include <cuda_fp16.h>
#include <cstdint>
#include <math.h>

// Problem: B=8, S=4096, D=1024, H=16, hd=64
#define MM 32768          // B*S
#define DD 1024
#define N_QKV 3072
#define NHEAD 16
#define HDIM 64
#define KK 1024

// GEMM tiling: single-pass fp16 (round-6 shape: CTA 128x128, warp 64x32)
#define BM 128
#define BN 128
#define BK 64
#define NCHUNK (KK / BK)      // 16
#define NSTAGE 3

// smem per stage: A 16KB (128 rows x 128B), B 16KB
#define OFF_A 0
#define OFF_B 16384
#define BUF_BYTES 32768
#define SMEM_DYN (NSTAGE * BUF_BYTES)     // 96 KB -> 2 CTAs/SM

// ---------------------------------------------------------------------------
// Scratch (device globals)
// ---------------------------------------------------------------------------
__device__ __half g_qkvh[(size_t)MM * N_QKV];   // fp16 qkv
__device__ __half g_xh[(size_t)MM * DD];
__device__ __half g_wq[(size_t)N_QKV * KK];     // W_qkv^T  [N][K] fp16
__device__ __half g_wo[(size_t)DD * KK];        // W_out^T
__device__ __half g_vh[(size_t)MM * DD];

// ---------------------------------------------------------------------------
// Helpers
// ---------------------------------------------------------------------------
__device__ __forceinline__ uint32_t smem_u32(const void* p) {
    uint32_t a;
    asm("{ .reg .u64 t; cvta.to.shared.u64 t, %1; cvt.u32.u64 %0, t; }"
        : "=r"(a) : "l"(p));
    return a;
}

__device__ __forceinline__ void cp16(uint32_t dst, const void* src) {
    asm volatile("cp.async.cg.shared.global [%0], [%1], 16;"
                 :: "r"(dst), "l"(src) : "memory");
}
__device__ __forceinline__ void cp_commit() {
    asm volatile("cp.async.commit_group;" ::: "memory");
}
template <int N>
__device__ __forceinline__ void cp_wait() {
    asm volatile("cp.async.wait_group %0;" :: "n"(N) : "memory");
}

#define LDX4(r, addr) \
    asm volatile("ldmatrix.sync.aligned.m8n8.x4.shared.b16 {%0,%1,%2,%3}, [%4];" \
        : "=r"((r)[0]), "=r"((r)[1]), "=r"((r)[2]), "=r"((r)[3]) : "r"(addr))

#define MMA16816(d, a, b) \
    asm volatile("mma.sync.aligned.m16n8k16.row.col.f32.f16.f16.f32 " \
        "{%0,%1,%2,%3}, {%4,%5,%6,%7}, {%8,%9}, {%0,%1,%2,%3};" \
        : "+f"((d)[0]), "+f"((d)[1]), "+f"((d)[2]), "+f"((d)[3]) \
        : "r"((a)[0]), "r"((a)[1]), "r"((a)[2]), "r"((a)[3]), \
          "r"((b)[0]), "r"((b)[1]))

// ---------------------------------------------------------------------------
// HMMA GEMM (single-pass fp16): C[M,Ntot] = A[M,K] @ B[Ntot,K]^T + bias
// fp32 accum, OutT output. CTA 128x128, warp 64x32 (2m x 4n), BK=64, SW128,
// 3-stage cp.async, 2 CTAs/SM, register-double-buffered fragments.
// ---------------------------------------------------------------------------
template <typename OutT>
__global__ __launch_bounds__(256, 2)
void gemm_hmma(const __half* __restrict__ Am, const __half* __restrict__ Bm,
               const float* __restrict__ bias, OutT* __restrict__ C, int Ntot)
{
    extern __shared__ char smem[];
    const uint32_t sb = smem_u32(smem);

    const int tid  = threadIdx.x;
    const int wid  = tid >> 5;
    const int lane = tid & 31;
    const int wm = (wid & 1) * 64;
    const int wn = (wid >> 1) * 32;

    const size_t m0 = (size_t)blockIdx.y * BM;
    const size_t n0 = (size_t)blockIdx.x * BN;

    // cp.async mapping: 128 rows x 128B per tile = 1024 x16B chunks; 4/thread
    const __half* srcA[4];
    const __half* srcB[4];
    uint32_t dstOff[4];
    #pragma unroll
    for (int t = 0; t < 4; t++) {
        int idx = tid + t * 256;
        int row = idx >> 3;              // 0..127
        int cq  = idx & 7;               // 16B chunk within 128B row
        srcA[t] = Am + (m0 + row) * KK + cq * 8;
        srcB[t] = Bm + (n0 + row) * KK + cq * 8;
        dstOff[t] = row * 128 + ((cq * 16) ^ ((row & 7) << 4));   // SW128
    }

    // ldmatrix offsets for ks=0; per-ks step XORs kx (in-row bits only)
    uint32_t offA[4], offB[2];
    #pragma unroll
    for (int tm = 0; tm < 4; tm++) {
        int row = wm + tm * 16 + (lane & 15);
        offA[tm] = row * 128 + ((((lane >> 4) << 4)) ^ ((row & 7) << 4));
    }
    #pragma unroll
    for (int tp = 0; tp < 2; tp++) {
        int row = wn + tp * 16 + ((lane >> 4) & 1) * 8 + (lane & 7);
        offB[tp] = row * 128 + ((((lane >> 3) & 1) * 16) ^ ((row & 7) << 4));
    }

    float acc[4][4][4];
    #pragma unroll
    for (int i = 0; i < 4; i++)
        #pragma unroll
        for (int j = 0; j < 4; j++)
            #pragma unroll
            for (int r = 0; r < 4; r++) acc[i][j][r] = 0.0f;

    // prefetch stages 0,1
    #pragma unroll
    for (int s = 0; s < 2; s++) {
        const uint32_t buf = sb + s * BUF_BYTES;
        const int koff = s * BK;
        #pragma unroll
        for (int t = 0; t < 4; t++) {
            cp16(buf + OFF_A + dstOff[t], srcA[t] + koff);
            cp16(buf + OFF_B + dstOff[t], srcB[t] + koff);
        }
        cp_commit();
    }

    // fragment double buffers
    uint32_t aaE[4][4], bbE[4][2], aaO[4][4], bbO[4][2];

    int bufIdx = 0;
    #pragma unroll 1
    for (int c = 0; c < NCHUNK; ++c) {
        if (c + 2 < NCHUNK) {
            int pidx = bufIdx + 2; if (pidx >= NSTAGE) pidx -= NSTAGE;
            const uint32_t nbuf = sb + pidx * BUF_BYTES;
            const int koff = (c + 2) * BK;
            #pragma unroll
            for (int t = 0; t < 4; t++) {
                cp16(nbuf + OFF_A + dstOff[t], srcA[t] + koff);
                cp16(nbuf + OFF_B + dstOff[t], srcB[t] + koff);
            }
        }
        cp_commit();
        cp_wait<2>();
        __syncthreads();

        const uint32_t bufA = sb + bufIdx * BUF_BYTES + OFF_A;
        const uint32_t bufB = sb + bufIdx * BUF_BYTES + OFF_B;

        // --- software-pipelined ks loop (4 steps, fragments double-buffered)
        #define LOAD_FRAG(AA, BB, kx) do {                                   \
            _Pragma("unroll")                                                \
            for (int tm = 0; tm < 4; tm++)                                   \
                LDX4(AA[tm], bufA + (offA[tm] ^ (kx)));                      \
            _Pragma("unroll")                                                \
            for (int tp = 0; tp < 2; tp++) {                                 \
                uint32_t r_[4];                                              \
                LDX4(r_, bufB + (offB[tp] ^ (kx)));                          \
                BB[2 * tp][0] = r_[0]; BB[2 * tp][1] = r_[1];                \
                BB[2 * tp + 1][0] = r_[2]; BB[2 * tp + 1][1] = r_[3];        \
            }                                                                \
        } while (0)

        #define MMA_ALL(AA, BB) do {                                         \
            _Pragma("unroll")                                                \
            for (int tm = 0; tm < 4; tm++)                                   \
                _Pragma("unroll")                                            \
                for (int tn = 0; tn < 4; tn++)                               \
                    MMA16816(acc[tm][tn], AA[tm], BB[tn]);                   \
        } while (0)

        LOAD_FRAG(aaE, bbE, 0);       // ks0
        LOAD_FRAG(aaO, bbO, 32);      // ks1 (hides under ks0 MMAs)
        MMA_ALL(aaE, bbE);            // ks0
        LOAD_FRAG(aaE, bbE, 64);      // ks2
        MMA_ALL(aaO, bbO);            // ks1
        LOAD_FRAG(aaO, bbO, 96);      // ks3
        MMA_ALL(aaE, bbE);            // ks2
        MMA_ALL(aaO, bbO);            // ks3

        #undef LOAD_FRAG
        #undef MMA_ALL

        __syncthreads();
        if (++bufIdx == NSTAGE) bufIdx = 0;
    }

    // epilogue: bias + store
    const int rq = lane >> 2;
    const int cp = (lane & 3) * 2;
    #pragma unroll
    for (int tn = 0; tn < 4; tn++) {
        const int col = (int)n0 + wn + tn * 8 + cp;
        const float b0 = bias[col], b1 = bias[col + 1];
        #pragma unroll
        for (int tm = 0; tm < 4; tm++) {
            const size_t r1 = m0 + wm + tm * 16 + rq;
            float2 o0, o1;
            o0.x = acc[tm][tn][0] + b0;
            o0.y = acc[tm][tn][1] + b1;
            o1.x = acc[tm][tn][2] + b0;
            o1.y = acc[tm][tn][3] + b1;
            if constexpr (sizeof(OutT) == 4) {
                *reinterpret_cast<float2*>((float*)C + r1 * Ntot + col) = o0;
                *reinterpret_cast<float2*>((float*)C + (r1 + 8) * Ntot + col) = o1;
            } else {
                *reinterpret_cast<__half2*>((__half*)C + r1 * Ntot + col) =
                    __floats2half2_rn(o0.x, o0.y);
                *reinterpret_cast<__half2*>((__half*)C + (r1 + 8) * Ntot + col) =
                    __floats2half2_rn(o1.x, o1.y);
            }
        }
    }
}

// ---------------------------------------------------------------------------
// fp32 -> fp16 convert (x)
// ---------------------------------------------------------------------------
__global__ __launch_bounds__(256)
void conv_h(const float* __restrict__ in, __half* __restrict__ hi)
{
    size_t i0 = ((size_t)blockIdx.x * 256 + threadIdx.x) * 4;
    float4 v = *reinterpret_cast<const float4*>(in + i0);
    __half2 a, b;
    a.x = __float2half_rn(v.x); a.y = __float2half_rn(v.y);
    b.x = __float2half_rn(v.z); b.y = __float2half_rn(v.w);
    reinterpret_cast<__half2*>(hi + i0)[0] = a;
    reinterpret_cast<__half2*>(hi + i0)[1] = b;
}

// ---------------------------------------------------------------------------
// W[K][N] fp32 -> W^T[N][K] fp16, tiled & coalesced
// ---------------------------------------------------------------------------
__global__ __launch_bounds__(256)
void transpose_h(const float* __restrict__ W, __half* __restrict__ WT, int N)
{
    __shared__ float tile[32][33];
    const int k0 = blockIdx.x * 32;
    const int n0 = blockIdx.y * 32;
    const int tx = threadIdx.x, ty = threadIdx.y;
    #pragma unroll
    for (int j = 0; j < 4; j++)
        tile[ty + j * 8][tx] = W[(size_t)(k0 + ty + j * 8) * N + n0 + tx];
    __syncthreads();
    #pragma unroll
    for (int j = 0; j < 4; j++)
        WT[(size_t)(n0 + ty + j * 8) * KK + k0 + tx] =
            __float2half_rn(tile[tx][ty + j * 8]);
}

// ---------------------------------------------------------------------------
// Per-token 16x16 head attention (fp16 qkv in, fp16 val out).
// ---------------------------------------------------------------------------
__global__ __launch_bounds__(256)
void attn_kernel()
{
    __shared__ float sq[NHEAD][HDIM];
    __shared__ float skT[HDIM][NHEAD + 1];
    __shared__ float sv[NHEAD][HDIM];
    __shared__ float sat[NHEAD][NHEAD];

    const size_t p = blockIdx.x;
    const __half2* row2 = reinterpret_cast<const __half2*>(g_qkvh + p * (size_t)N_QKV);
    const int tid = threadIdx.x;

    #pragma unroll
    for (int t = 0; t < 6; t++) {
        int i2 = tid + t * 256;
        float2 f = __half22float2(row2[i2]);
        int h = i2 / 96;
        int r = 2 * (i2 - h * 96);
        if (r < 64) {
            sq[h][r] = f.x; sq[h][r + 1] = f.y;
        } else if (r < 128) {
            int rr = r - 64;
            skT[rr][h] = f.x; skT[rr + 1][h] = f.y;
        } else {
            int rr = r - 128;
            sv[h][rr] = f.x; sv[h][rr + 1] = f.y;
        }
    }
    __syncthreads();

    const int i = tid >> 4;
    const int j = tid & 15;
    float s = 0.0f;
    #pragma unroll 8
    for (int d = 0; d < HDIM; d++) s += sq[i][d] * skT[d][j];
    s *= 0.125f;

    float mx = s;
    #pragma unroll
    for (int m = 8; m >= 1; m >>= 1)
        mx = fmaxf(mx, __shfl_xor_sync(0xffffffffu, mx, m));
    float e = __expf(s - mx);
    float sum = e;
    #pragma unroll
    for (int m = 8; m >= 1; m >>= 1)
        sum += __shfl_xor_sync(0xffffffffu, sum, m);
    sat[i][j] = e / sum;
    __syncthreads();

    __half2* vh2 = reinterpret_cast<__half2*>(g_vh + p * (size_t)DD);
    #pragma unroll
    for (int t = 0; t < 2; t++) {
        int i2 = tid + t * 256;
        int oi = i2 >> 5;
        int d  = (i2 & 31) * 2;
        float a0 = 0.0f, a1 = 0.0f;
        #pragma unroll
        for (int jj = 0; jj < NHEAD; jj++) {
            float w = sat[oi][jj];
            a0 += w * sv[jj][d];
            a1 += w * sv[jj][d + 1];
        }
        vh2[i2] = __floats2half2_rn(a0, a1);
    }
}

// ---------------------------------------------------------------------------
// Launch: x, W_qkv, b_qkv, W_out, b_out
// ---------------------------------------------------------------------------
extern "C" void kernel_launch(void* const* d_in, const int* in_sizes, int n_in,
                              void* d_out, int out_size)
{
    const float* x     = (const float*)d_in[0];
    const float* W_qkv = (const float*)d_in[1];
    const float* b_qkv = (const float*)d_in[2];
    const float* W_out = (const float*)d_in[3];
    const float* b_out = (const float*)d_in[4];
    float* out = (float*)d_out;

    __half *qkvh, *xh, *wq, *wo, *vh;
    cudaGetSymbolAddress((void**)&qkvh, g_qkvh);
    cudaGetSymbolAddress((void**)&xh, g_xh);
    cudaGetSymbolAddress((void**)&wq, g_wq);
    cudaGetSymbolAddress((void**)&wo, g_wo);
    cudaGetSymbolAddress((void**)&vh, g_vh);

    cudaFuncSetAttribute(gemm_hmma<__half>,
                         cudaFuncAttributeMaxDynamicSharedMemorySize, SMEM_DYN);
    cudaFuncSetAttribute(gemm_hmma<float>,
                         cudaFuncAttributeMaxDynamicSharedMemorySize, SMEM_DYN);

    // conversions
    conv_h<<<(size_t)MM * DD / (256 * 4), 256>>>(x, xh);
    transpose_h<<<dim3(KK / 32, N_QKV / 32), dim3(32, 8)>>>(W_qkv, wq, N_QKV);
    transpose_h<<<dim3(KK / 32, DD / 32), dim3(32, 8)>>>(W_out, wo, DD);

    // GEMM1: qkv(fp16) = x @ W_qkv + b_qkv   (32768 x 3072, K=1024)
    gemm_hmma<__half><<<dim3(N_QKV / BN, MM / BM), 256, SMEM_DYN>>>(
        xh, wq, b_qkv, qkvh, N_QKV);

    // attention per token
    attn_kernel<<<MM, 256>>>();

    // GEMM2: out = val @ W_out + b_out (32768 x 1024, K=1024)
    gemm_hmma<float><<<dim3(DD / BN, MM / BM), 256, SMEM_DYN>>>(
        vh, wo, b_out, out, DD);
}

// round 10
// speedup vs baseline: 1.5373x; 1.5373x over previous
#include <cuda_runtime.h>
#include <cuda_fp16.h>
#include <cstdint>
#include <math.h>

// Problem: B=8, S=4096, D=1024, H=16, hd=64
#define MM 32768          // B*S
#define DD 1024
#define N_QKV 3072
#define NHEAD 16
#define HDIM 64
#define KK 1024

// GEMM tiling: single-pass fp16 (round-6 shape: CTA 128x128, warp 64x32)
#define BM 128
#define BN 128
#define BK 64
#define NCHUNK (KK / BK)      // 16
#define NSTAGE 3

// smem per stage: A 16KB (128 rows x 128B), B 16KB
#define OFF_A 0
#define OFF_B 16384
#define BUF_BYTES 32768
#define SMEM_DYN (NSTAGE * BUF_BYTES)     // 96 KB -> 2 CTAs/SM

// ---------------------------------------------------------------------------
// Scratch (device globals)
// ---------------------------------------------------------------------------
__device__ __half g_qkvh[(size_t)MM * N_QKV];   // fp16 qkv
__device__ __half g_xh[(size_t)MM * DD];
__device__ __half g_wq[(size_t)N_QKV * KK];     // W_qkv^T  [N][K] fp16
__device__ __half g_wo[(size_t)DD * KK];        // W_out^T
__device__ __half g_vh[(size_t)MM * DD];

// ---------------------------------------------------------------------------
// Helpers
// ---------------------------------------------------------------------------
__device__ __forceinline__ uint32_t smem_u32(const void* p) {
    uint32_t a;
    asm("{ .reg .u64 t; cvta.to.shared.u64 t, %1; cvt.u32.u64 %0, t; }"
        : "=r"(a) : "l"(p));
    return a;
}

__device__ __forceinline__ void cp16(uint32_t dst, const void* src) {
    asm volatile("cp.async.cg.shared.global [%0], [%1], 16;"
                 :: "r"(dst), "l"(src) : "memory");
}
__device__ __forceinline__ void cp_commit() {
    asm volatile("cp.async.commit_group;" ::: "memory");
}
template <int N>
__device__ __forceinline__ void cp_wait() {
    asm volatile("cp.async.wait_group %0;" :: "n"(N) : "memory");
}

#define LDX4(r, addr) \
    asm volatile("ldmatrix.sync.aligned.m8n8.x4.shared.b16 {%0,%1,%2,%3}, [%4];" \
        : "=r"((r)[0]), "=r"((r)[1]), "=r"((r)[2]), "=r"((r)[3]) : "r"(addr))

#define MMA16816(d, a, b) \
    asm volatile("mma.sync.aligned.m16n8k16.row.col.f32.f16.f16.f32 " \
        "{%0,%1,%2,%3}, {%4,%5,%6,%7}, {%8,%9}, {%0,%1,%2,%3};" \
        : "+f"((d)[0]), "+f"((d)[1]), "+f"((d)[2]), "+f"((d)[3]) \
        : "r"((a)[0]), "r"((a)[1]), "r"((a)[2]), "r"((a)[3]), \
          "r"((b)[0]), "r"((b)[1]))

// ---------------------------------------------------------------------------
// HMMA GEMM (single-pass fp16): C[M,Ntot] = A[M,K] @ B[Ntot,K]^T + bias
// fp32 accum, OutT output. CTA 128x128, warp 64x32 (2m x 4n), BK=64, SW128,
// 3-stage cp.async, 2 CTAs/SM, ONE __syncthreads per chunk (prefetch issued
// after the barrier: its target buffer's readers all finished last iter).
// ---------------------------------------------------------------------------
template <typename OutT>
__global__ __launch_bounds__(256, 2)
void gemm_hmma(const __half* __restrict__ Am, const __half* __restrict__ Bm,
               const float* __restrict__ bias, OutT* __restrict__ C, int Ntot)
{
    extern __shared__ char smem[];
    const uint32_t sb = smem_u32(smem);

    const int tid  = threadIdx.x;
    const int wid  = tid >> 5;
    const int lane = tid & 31;
    const int wm = (wid & 1) * 64;
    const int wn = (wid >> 1) * 32;

    const size_t m0 = (size_t)blockIdx.y * BM;
    const size_t n0 = (size_t)blockIdx.x * BN;

    // cp.async mapping: 128 rows x 128B per tile = 1024 x16B chunks; 4/thread
    const __half* srcA[4];
    const __half* srcB[4];
    uint32_t dstOff[4];
    #pragma unroll
    for (int t = 0; t < 4; t++) {
        int idx = tid + t * 256;
        int row = idx >> 3;              // 0..127
        int cq  = idx & 7;               // 16B chunk within 128B row
        srcA[t] = Am + (m0 + row) * KK + cq * 8;
        srcB[t] = Bm + (n0 + row) * KK + cq * 8;
        dstOff[t] = row * 128 + ((cq * 16) ^ ((row & 7) << 4));   // SW128
    }

    // ldmatrix offsets for ks=0; per-ks step XORs kx (in-row bits only)
    uint32_t offA[4], offB[2];
    #pragma unroll
    for (int tm = 0; tm < 4; tm++) {
        int row = wm + tm * 16 + (lane & 15);
        offA[tm] = row * 128 + ((((lane >> 4) << 4)) ^ ((row & 7) << 4));
    }
    #pragma unroll
    for (int tp = 0; tp < 2; tp++) {
        int row = wn + tp * 16 + ((lane >> 4) & 1) * 8 + (lane & 7);
        offB[tp] = row * 128 + ((((lane >> 3) & 1) * 16) ^ ((row & 7) << 4));
    }

    float acc[4][4][4];
    #pragma unroll
    for (int i = 0; i < 4; i++)
        #pragma unroll
        for (int j = 0; j < 4; j++)
            #pragma unroll
            for (int r = 0; r < 4; r++) acc[i][j][r] = 0.0f;

    // prefetch stages 0,1
    #pragma unroll
    for (int s = 0; s < 2; s++) {
        const uint32_t buf = sb + s * BUF_BYTES;
        const int koff = s * BK;
        #pragma unroll
        for (int t = 0; t < 4; t++) {
            cp16(buf + OFF_A + dstOff[t], srcA[t] + koff);
            cp16(buf + OFF_B + dstOff[t], srcB[t] + koff);
        }
        cp_commit();
    }

    int bufIdx = 0;
    #pragma unroll 1
    for (int c = 0; c < NCHUNK; ++c) {
        cp_wait<1>();
        __syncthreads();

        // prefetch stage c+2 into buf (bufIdx+2)%3 — read last at iter c-1,
        // and every warp has passed the barrier above, so WAR is safe.
        if (c + 2 < NCHUNK) {
            int pidx = bufIdx + 2; if (pidx >= NSTAGE) pidx -= NSTAGE;
            const uint32_t nbuf = sb + pidx * BUF_BYTES;
            const int koff = (c + 2) * BK;
            #pragma unroll
            for (int t = 0; t < 4; t++) {
                cp16(nbuf + OFF_A + dstOff[t], srcA[t] + koff);
                cp16(nbuf + OFF_B + dstOff[t], srcB[t] + koff);
            }
        }
        cp_commit();      // always commit so wait counts stay exact

        const uint32_t buf = sb + bufIdx * BUF_BYTES;
        #pragma unroll
        for (int ks = 0; ks < 4; ks++) {
            const uint32_t kx = ks * 32;
            uint32_t aa[4][4], bb[4][2];

            #pragma unroll
            for (int tm = 0; tm < 4; tm++)
                LDX4(aa[tm], buf + OFF_A + (offA[tm] ^ kx));
            #pragma unroll
            for (int tp = 0; tp < 2; tp++) {
                uint32_t r[4];
                LDX4(r, buf + OFF_B + (offB[tp] ^ kx));
                bb[2 * tp][0] = r[0]; bb[2 * tp][1] = r[1];
                bb[2 * tp + 1][0] = r[2]; bb[2 * tp + 1][1] = r[3];
            }
            #pragma unroll
            for (int tm = 0; tm < 4; tm++)
                #pragma unroll
                for (int tn = 0; tn < 4; tn++)
                    MMA16816(acc[tm][tn], aa[tm], bb[tn]);
        }
        if (++bufIdx == NSTAGE) bufIdx = 0;
    }

    // epilogue: bias + store
    const int rq = lane >> 2;
    const int cp = (lane & 3) * 2;
    #pragma unroll
    for (int tn = 0; tn < 4; tn++) {
        const int col = (int)n0 + wn + tn * 8 + cp;
        const float b0 = bias[col], b1 = bias[col + 1];
        #pragma unroll
        for (int tm = 0; tm < 4; tm++) {
            const size_t r1 = m0 + wm + tm * 16 + rq;
            float2 o0, o1;
            o0.x = acc[tm][tn][0] + b0;
            o0.y = acc[tm][tn][1] + b1;
            o1.x = acc[tm][tn][2] + b0;
            o1.y = acc[tm][tn][3] + b1;
            if constexpr (sizeof(OutT) == 4) {
                *reinterpret_cast<float2*>((float*)C + r1 * Ntot + col) = o0;
                *reinterpret_cast<float2*>((float*)C + (r1 + 8) * Ntot + col) = o1;
            } else {
                *reinterpret_cast<__half2*>((__half*)C + r1 * Ntot + col) =
                    __floats2half2_rn(o0.x, o0.y);
                *reinterpret_cast<__half2*>((__half*)C + (r1 + 8) * Ntot + col) =
                    __floats2half2_rn(o1.x, o1.y);
            }
        }
    }
}

// ---------------------------------------------------------------------------
// fp32 -> fp16 convert (x)
// ---------------------------------------------------------------------------
__global__ __launch_bounds__(256)
void conv_h(const float* __restrict__ in, __half* __restrict__ hi)
{
    size_t i0 = ((size_t)blockIdx.x * 256 + threadIdx.x) * 4;
    float4 v = *reinterpret_cast<const float4*>(in + i0);
    __half2 a, b;
    a.x = __float2half_rn(v.x); a.y = __float2half_rn(v.y);
    b.x = __float2half_rn(v.z); b.y = __float2half_rn(v.w);
    reinterpret_cast<__half2*>(hi + i0)[0] = a;
    reinterpret_cast<__half2*>(hi + i0)[1] = b;
}

// ---------------------------------------------------------------------------
// W[K][N] fp32 -> W^T[N][K] fp16, tiled & coalesced
// ---------------------------------------------------------------------------
__global__ __launch_bounds__(256)
void transpose_h(const float* __restrict__ W, __half* __restrict__ WT, int N)
{
    __shared__ float tile[32][33];
    const int k0 = blockIdx.x * 32;
    const int n0 = blockIdx.y * 32;
    const int tx = threadIdx.x, ty = threadIdx.y;
    #pragma unroll
    for (int j = 0; j < 4; j++)
        tile[ty + j * 8][tx] = W[(size_t)(k0 + ty + j * 8) * N + n0 + tx];
    __syncthreads();
    #pragma unroll
    for (int j = 0; j < 4; j++)
        WT[(size_t)(n0 + ty + j * 8) * KK + k0 + tx] =
            __float2half_rn(tile[tx][ty + j * 8]);
}

// ---------------------------------------------------------------------------
// Per-token 16x16 head attention (fp16 qkv in, fp16 val out).
// ---------------------------------------------------------------------------
__global__ __launch_bounds__(256)
void attn_kernel()
{
    __shared__ float sq[NHEAD][HDIM];
    __shared__ float skT[HDIM][NHEAD + 1];
    __shared__ float sv[NHEAD][HDIM];
    __shared__ float sat[NHEAD][NHEAD];

    const size_t p = blockIdx.x;
    const __half2* row2 = reinterpret_cast<const __half2*>(g_qkvh + p * (size_t)N_QKV);
    const int tid = threadIdx.x;

    #pragma unroll
    for (int t = 0; t < 6; t++) {
        int i2 = tid + t * 256;
        float2 f = __half22float2(row2[i2]);
        int h = i2 / 96;
        int r = 2 * (i2 - h * 96);
        if (r < 64) {
            sq[h][r] = f.x; sq[h][r + 1] = f.y;
        } else if (r < 128) {
            int rr = r - 64;
            skT[rr][h] = f.x; skT[rr + 1][h] = f.y;
        } else {
            int rr = r - 128;
            sv[h][rr] = f.x; sv[h][rr + 1] = f.y;
        }
    }
    __syncthreads();

    const int i = tid >> 4;
    const int j = tid & 15;
    float s = 0.0f;
    #pragma unroll 8
    for (int d = 0; d < HDIM; d++) s += sq[i][d] * skT[d][j];
    s *= 0.125f;

    float mx = s;
    #pragma unroll
    for (int m = 8; m >= 1; m >>= 1)
        mx = fmaxf(mx, __shfl_xor_sync(0xffffffffu, mx, m));
    float e = __expf(s - mx);
    float sum = e;
    #pragma unroll
    for (int m = 8; m >= 1; m >>= 1)
        sum += __shfl_xor_sync(0xffffffffu, sum, m);
    sat[i][j] = e / sum;
    __syncthreads();

    __half2* vh2 = reinterpret_cast<__half2*>(g_vh + p * (size_t)DD);
    #pragma unroll
    for (int t = 0; t < 2; t++) {
        int i2 = tid + t * 256;
        int oi = i2 >> 5;
        int d  = (i2 & 31) * 2;
        float a0 = 0.0f, a1 = 0.0f;
        #pragma unroll
        for (int jj = 0; jj < NHEAD; jj++) {
            float w = sat[oi][jj];
            a0 += w * sv[jj][d];
            a1 += w * sv[jj][d + 1];
        }
        vh2[i2] = __floats2half2_rn(a0, a1);
    }
}

// ---------------------------------------------------------------------------
// Launch: x, W_qkv, b_qkv, W_out, b_out
// ---------------------------------------------------------------------------
extern "C" void kernel_launch(void* const* d_in, const int* in_sizes, int n_in,
                              void* d_out, int out_size)
{
    const float* x     = (const float*)d_in[0];
    const float* W_qkv = (const float*)d_in[1];
    const float* b_qkv = (const float*)d_in[2];
    const float* W_out = (const float*)d_in[3];
    const float* b_out = (const float*)d_in[4];
    float* out = (float*)d_out;

    __half *qkvh, *xh, *wq, *wo, *vh;
    cudaGetSymbolAddress((void**)&qkvh, g_qkvh);
    cudaGetSymbolAddress((void**)&xh, g_xh);
    cudaGetSymbolAddress((void**)&wq, g_wq);
    cudaGetSymbolAddress((void**)&wo, g_wo);
    cudaGetSymbolAddress((void**)&vh, g_vh);

    cudaFuncSetAttribute(gemm_hmma<__half>,
                         cudaFuncAttributeMaxDynamicSharedMemorySize, SMEM_DYN);
    cudaFuncSetAttribute(gemm_hmma<float>,
                         cudaFuncAttributeMaxDynamicSharedMemorySize, SMEM_DYN);

    // conversions
    conv_h<<<(size_t)MM * DD / (256 * 4), 256>>>(x, xh);
    transpose_h<<<dim3(KK / 32, N_QKV / 32), dim3(32, 8)>>>(W_qkv, wq, N_QKV);
    transpose_h<<<dim3(KK / 32, DD / 32), dim3(32, 8)>>>(W_out, wo, DD);

    // GEMM1: qkv(fp16) = x @ W_qkv + b_qkv   (32768 x 3072, K=1024)
    gemm_hmma<__half><<<dim3(N_QKV / BN, MM / BM), 256, SMEM_DYN>>>(
        xh, wq, b_qkv, qkvh, N_QKV);

    // attention per token
    attn_kernel<<<MM, 256>>>();

    // GEMM2: out = val @ W_out + b_out (32768 x 1024, K=1024)
    gemm_hmma<float><<<dim3(DD / BN, MM / BM), 256, SMEM_DYN>>>(
        vh, wo, b_out, out, DD);
}